// round 14
// baseline (speedup 1.0000x reference)
#include <cuda_runtime.h>
#include <cstdint>

// HaarWaveletTopK on GB300 (sm_103a) — threshold-candidate design, v8 (fused).
// Single kernel: float4 streaming Haar (main + zero detail) + rare threshold
// candidate pushes; the last-finishing block of each 128-column group runs the
// REDUX top-8 selection + sparse scatter for its group (threadfence pattern).
// x: (B=8, T=8192, F=512) fp32.  out = [main | detail], each (B,T,F).

#define DIM_B 8
#define DIM_T 8192
#define DIM_T2 4096
#define DIM_F 512
#define DIM_F4 (DIM_F / 4)              // 128 float4 per row

#define TOPK 8
#define NC 32                            // t-chunks (grid z) = blocks per group
#define T_PER_CHUNK (DIM_T2 / NC)        // 128
#define TSEG 8                           // warps per block
#define NTHREADS (32 * TSEG)             // 256
#define T_PER_THREAD (T_PER_CHUNK / TSEG)    // 16
#define UNROLL 4

#define NGRPX 4                          // gridDim.x
#define NGRP (NGRPX * DIM_B)             // 32 column groups
#define COLS_PER_GRP 128

#define CAP 96                           // max candidates kept per column
// |e-o| ~ N(0,2). THRESH = 3.6 => p ~= 0.0109/value, mean ~= 45 cands/col.
// P(count < 8) ~ 1e-14, P(count > 96) ~ 1e-14 per column.
#define THRESH 3.6f

typedef unsigned long long u64;
typedef unsigned int u32;

__device__ u32 g_count[DIM_B * DIM_F] = {};          // zero-init at load
__device__ u32 g_done[NGRP]           = {};          // zero-init at load
__device__ u64 g_cand[DIM_B * DIM_F * CAP];          // masked by count

__device__ __forceinline__ u64 pack_cand(float a, int t, float h)
{
    const u32 pay = ((u32)t << 1) | (h < 0.0f ? 1u : 0u);
    return ((u64)__float_as_uint(a) << 32) | pay;    // a >= 0 -> monotone
}

__device__ __forceinline__ void push_cand(int col, float a, int t, float h)
{
    const u32 slot = atomicAdd(&g_count[col], 1u);
    if (slot < CAP)
        g_cand[(size_t)col * CAP + slot] = pack_cand(a, t, h);
}

// Warp-collective: select top-8 of one column and scatter into detail.
__device__ __forceinline__ void select_and_scatter(
    int col, int lane,
    const float* __restrict__ x,
    float* __restrict__ out_det)
{
    const int b = col >> 9;
    const int f = col & (DIM_F - 1);
    const u32 count = g_count[col];
    u64 res = 0;                      // lane r ends holding rank-r winner

    if (count >= TOPK && count <= CAP) {
        const size_t base = (size_t)col * CAP;
        u64 v0 = 0, v1 = 0, v2 = 0;
        if (lane      < (int)count) v0 = g_cand[base + lane];
        if (lane + 32 < (int)count) v1 = g_cand[base + lane + 32];
        if (lane + 64 < (int)count) v2 = g_cand[base + lane + 64];

        u64 t;
        if (v0 < v1) { t = v0; v0 = v1; v1 = t; }
        if (v1 < v2) { t = v1; v1 = v2; v2 = t; }
        if (v0 < v1) { t = v0; v0 = v1; v1 = t; }

#pragma unroll
        for (int r = 0; r < TOPK; ++r) {
            const u32 key  = (u32)(v0 >> 32);
            const u32 kmax = __reduce_max_sync(0xFFFFFFFFu, key);
            const unsigned m = __ballot_sync(0xFFFFFFFFu, key == kmax && v0 != 0);
            const int winner = __ffs(m) - 1;
            const u64 win = __shfl_sync(0xFFFFFFFFu, v0, winner);
            if (lane == winner) { v0 = v1; v1 = v2; v2 = 0; }
            if (lane == r) res = win;
        }
    } else {
        // Exact fallback (statistically never): pk unique per t.
        const float* __restrict__ xb = x + (size_t)b * DIM_T * DIM_F + f;
        u64 prev = ~0ull;
        for (int r = 0; r < TOPK; ++r) {
            u64 best = 0;
            for (int t = lane; t < DIM_T2; t += 32) {
                const float e = xb[(size_t)(2 * t) * DIM_F];
                const float o = xb[(size_t)(2 * t) * DIM_F + DIM_F];
                const float h = e - o;
                const u64 pk  = pack_cand(fabsf(h), t, h);
                if (pk < prev && pk > best) best = pk;
            }
#pragma unroll
            for (int off = 16; off > 0; off >>= 1) {
                const u64 other = __shfl_xor_sync(0xFFFFFFFFu, best, off);
                if (other > best) best = other;
            }
            if (lane == r) res = best;
            prev = best;
        }
    }

    if (lane < TOPK && res != 0) {
        const u32 payv = (u32)res;
        float val = __uint_as_float((u32)(res >> 32)) * 0.5f;   // |h|*0.5
        if (payv & 1) val = -val;
        const int tt = (int)(payv >> 1);
        float* __restrict__ db = out_det + (size_t)b * DIM_T * DIM_F;
        const size_t r0 = (size_t)(2 * tt) * DIM_F + f;
        db[r0]         = val;
        db[r0 + DIM_F] = -val;
    }

    if (lane == 0) g_count[col] = 0u;     // restore invariant for next call
}

// ---------------------------------------------------------------------------
// Fused kernel.
// ---------------------------------------------------------------------------
__global__ __launch_bounds__(NTHREADS)
void haar_fused(const float4* __restrict__ x4,
                float4* __restrict__ m4,
                float4* __restrict__ d4,
                const float* __restrict__ x,
                float* __restrict__ det)
{
    const int lane = threadIdx.x & 31;
    const int ts   = threadIdx.x >> 5;
    const int g    = blockIdx.x * 32 + lane;     // float4 column (0..127)
    const int b    = blockIdx.y;
    const int c    = blockIdx.z;

    const float4* __restrict__ xb = x4 + (size_t)b * DIM_T * DIM_F4;
    float4* __restrict__ mb       = m4 + (size_t)b * DIM_T * DIM_F4;
    float4* __restrict__ db       = d4 + (size_t)b * DIM_T * DIM_F4;

    const int t0 = c * T_PER_CHUNK + ts * T_PER_THREAD;
    const float4 z4 = make_float4(0.f, 0.f, 0.f, 0.f);
    const int col0 = b * DIM_F + 4 * g;

    for (int ib = 0; ib < T_PER_THREAD; ib += UNROLL) {
        float4 e[UNROLL], o[UNROLL];

        // Front-batched: 2*UNROLL independent LDG.128 in flight.
#pragma unroll
        for (int i = 0; i < UNROLL; ++i) {
            const size_t re = (size_t)(2 * (t0 + ib + i)) * DIM_F4 + g;
            e[i] = xb[re];
            o[i] = xb[re + DIM_F4];
        }

#pragma unroll
        for (int i = 0; i < UNROLL; ++i) {
            const int t = t0 + ib + i;
            const size_t re = (size_t)(2 * t) * DIM_F4 + g;

            float4 low;
            low.x = (e[i].x + o[i].x) * 0.5f;
            low.y = (e[i].y + o[i].y) * 0.5f;
            low.z = (e[i].z + o[i].z) * 0.5f;
            low.w = (e[i].w + o[i].w) * 0.5f;

            mb[re]          = low;
            mb[re + DIM_F4] = low;
            db[re]          = z4;
            db[re + DIM_F4] = z4;

            const float hx = e[i].x - o[i].x;
            const float hy = e[i].y - o[i].y;
            const float hz = e[i].z - o[i].z;
            const float hw = e[i].w - o[i].w;
            const float ax = fabsf(hx), ay = fabsf(hy);
            const float az = fabsf(hz), aw = fabsf(hw);

            if (fmaxf(fmaxf(ax, ay), fmaxf(az, aw)) > THRESH) {   // rare-ish
                if (ax > THRESH) push_cand(col0,     ax, t, hx);
                if (ay > THRESH) push_cand(col0 + 1, ay, t, hy);
                if (az > THRESH) push_cand(col0 + 2, az, t, hz);
                if (aw > THRESH) push_cand(col0 + 3, aw, t, hw);
            }
        }
    }

    // ---- Group completion: last block of (x,b) group runs the selection ----
    const int grp = b * NGRPX + blockIdx.x;
    __shared__ u32 s_last;
    __syncthreads();                      // all this block's work issued
    if (threadIdx.x == 0) {
        __threadfence();                  // make our stores visible first
        s_last = (atomicAdd(&g_done[grp], 1u) == NC - 1) ? 1u : 0u;
    }
    __syncthreads();
    if (s_last == 0u) return;

    if (threadIdx.x == 0) g_done[grp] = 0u;   // reset for next replay
    __threadfence();                          // acquire side of the pattern

    // 8 warps x 16 columns = this group's 128 columns.
    const int fbase = b * DIM_F + blockIdx.x * COLS_PER_GRP;
#pragma unroll 1
    for (int i = 0; i < COLS_PER_GRP / TSEG; ++i)
        select_and_scatter(fbase + ts * (COLS_PER_GRP / TSEG) + i, lane, x, det);
}

extern "C" void kernel_launch(void* const* d_in, const int* in_sizes, int n_in,
                              void* d_out, int out_size)
{
    const float* x = (const float*)d_in[0];
    float* out = (float*)d_out;
    const size_t N = (size_t)out_size / 2;    // elements in `main`
    float* det = out + N;

    dim3 grid(NGRPX, DIM_B, NC);              // 4 x 8 x 32 = 1024 blocks
    haar_fused<<<grid, NTHREADS>>>((const float4*)x,
                                   (float4*)out,
                                   (float4*)det,
                                   x, det);
}

// round 17
// speedup vs baseline: 1.5048x; 1.5048x over previous
#include <cuda_runtime.h>
#include <cstdint>

// HaarWaveletTopK on GB300 (sm_103a) — threshold-candidate design, v9.
// = R12 (best: 77.9us) with 32-bit address arithmetic in pass1's hot loop
//   (fewer address regs -> possibly 5 blocks/SM instead of 4; no forcing).
// Pass1: float4 streaming Haar (main + zero detail) + rare threshold pushes.
// Pass2: warp-per-column REDUX top-8 select + sparse scatter; exact fallback.
// x: (B=8, T=8192, F=512) fp32.  out = [main | detail], each (B,T,F).

#define DIM_B 8
#define DIM_T 8192
#define DIM_T2 4096
#define DIM_F 512
#define DIM_F4 (DIM_F / 4)              // 128 float4 per row

#define TOPK 8
#define NC 32                            // t-chunks (grid z)
#define T_PER_CHUNK (DIM_T2 / NC)        // 128
#define TSEG 8                           // warps per block
#define NTHREADS (32 * TSEG)             // 256
#define T_PER_THREAD (T_PER_CHUNK / TSEG)    // 16
#define UNROLL 4

#define CAP 96                           // max candidates kept per column
// |e-o| ~ N(0,2). THRESH = 3.6 => p ~= 0.0109/value, mean ~= 45 cands/col.
// P(count < 8) ~ 1e-14, P(count > 96) ~ 1e-14 per column.
#define THRESH 3.6f

typedef unsigned long long u64;
typedef unsigned int u32;

__device__ u32 g_count[DIM_B * DIM_F] = {};          // zero-init at load
__device__ u64 g_cand[DIM_B * DIM_F * CAP];          // masked by count

__device__ __forceinline__ u64 pack_cand(float a, int t, float h)
{
    const u32 pay = ((u32)t << 1) | (h < 0.0f ? 1u : 0u);
    return ((u64)__float_as_uint(a) << 32) | pay;    // a >= 0 -> monotone
}

__device__ __forceinline__ void push_cand(int col, float a, int t, float h)
{
    const u32 slot = atomicAdd(&g_count[col], 1u);
    if (slot < CAP)
        g_cand[(size_t)col * CAP + slot] = pack_cand(a, t, h);
}

// ---------------------------------------------------------------------------
// Pass 1: float4 streaming transform, front-batched 128-bit loads.
// All intra-batch offsets fit in u32 (max 2^20 float4 elements).
// ---------------------------------------------------------------------------
__global__ __launch_bounds__(NTHREADS)
void haar_pass1(const float4* __restrict__ x4,
                float4* __restrict__ m4,
                float4* __restrict__ d4)
{
    const int lane = threadIdx.x & 31;
    const int ts   = threadIdx.x >> 5;
    const u32 g    = blockIdx.x * 32 + lane;     // float4 column (0..127)
    const int b    = blockIdx.y;
    const int c    = blockIdx.z;

    const float4* __restrict__ xb = x4 + (size_t)b * DIM_T * DIM_F4;
    float4* __restrict__ mb       = m4 + (size_t)b * DIM_T * DIM_F4;
    float4* __restrict__ db       = d4 + (size_t)b * DIM_T * DIM_F4;

    const int t0 = c * T_PER_CHUNK + ts * T_PER_THREAD;
    const float4 z4 = make_float4(0.f, 0.f, 0.f, 0.f);
    const int col0 = b * DIM_F + 4 * (int)g;

    for (int ib = 0; ib < T_PER_THREAD; ib += UNROLL) {
        float4 e[UNROLL], o[UNROLL];

        // Front-batched: 2*UNROLL independent LDG.128 in flight.
#pragma unroll
        for (int i = 0; i < UNROLL; ++i) {
            const u32 re = (u32)(2 * (t0 + ib + i)) * DIM_F4 + g;
            e[i] = xb[re];
            o[i] = xb[re + DIM_F4];
        }

#pragma unroll
        for (int i = 0; i < UNROLL; ++i) {
            const int t = t0 + ib + i;
            const u32 re = (u32)(2 * t) * DIM_F4 + g;

            float4 low;
            low.x = (e[i].x + o[i].x) * 0.5f;
            low.y = (e[i].y + o[i].y) * 0.5f;
            low.z = (e[i].z + o[i].z) * 0.5f;
            low.w = (e[i].w + o[i].w) * 0.5f;

            mb[re]          = low;
            mb[re + DIM_F4] = low;
            db[re]          = z4;
            db[re + DIM_F4] = z4;

            const float hx = e[i].x - o[i].x;
            const float hy = e[i].y - o[i].y;
            const float hz = e[i].z - o[i].z;
            const float hw = e[i].w - o[i].w;
            const float ax = fabsf(hx), ay = fabsf(hy);
            const float az = fabsf(hz), aw = fabsf(hw);

            if (fmaxf(fmaxf(ax, ay), fmaxf(az, aw)) > THRESH) {   // rare-ish
                if (ax > THRESH) push_cand(col0,     ax, t, hx);
                if (ay > THRESH) push_cand(col0 + 1, ay, t, hy);
                if (az > THRESH) push_cand(col0 + 2, az, t, hz);
                if (aw > THRESH) push_cand(col0 + 3, aw, t, hw);
            }
        }
    }
}

// ---------------------------------------------------------------------------
// Pass 2: one warp per (b,f) column. Normal path: REDUX-based top-8 select.
// Fallback (statistically never): 8 scans of "warp-max strictly below prev".
// ---------------------------------------------------------------------------
__global__ __launch_bounds__(256)
void haar_pass2(const float* __restrict__ x,
                float* __restrict__ out_det)
{
    const int wid_in_blk = threadIdx.x >> 5;
    const int lane       = threadIdx.x & 31;
    const int col        = blockIdx.x * 8 + wid_in_blk;   // 0..4095
    const int b          = col >> 9;
    const int f          = col & (DIM_F - 1);

    const u32 count = g_count[col];
    u64 res = 0;                      // lane r ends holding rank-r winner

    if (count >= TOPK && count <= CAP) {
        // ---- Normal path: masked coalesced loads (<=3 per lane) ----
        const size_t base = (size_t)col * CAP;
        u64 v0 = 0, v1 = 0, v2 = 0;
        if (lane      < (int)count) v0 = g_cand[base + lane];
        if (lane + 32 < (int)count) v1 = g_cand[base + lane + 32];
        if (lane + 64 < (int)count) v2 = g_cand[base + lane + 64];

        // Sort 3 descending per lane (u64 compare: key-major, pay-minor).
        u64 t;
        if (v0 < v1) { t = v0; v0 = v1; v1 = t; }
        if (v1 < v2) { t = v1; v1 = v2; v2 = t; }
        if (v0 < v1) { t = v0; v0 = v1; v1 = t; }

        // 8 rounds: REDUX max over 32-bit keys, fetch winner's u64, pop.
#pragma unroll
        for (int r = 0; r < TOPK; ++r) {
            const u32 key  = (u32)(v0 >> 32);
            const u32 kmax = __reduce_max_sync(0xFFFFFFFFu, key);
            const unsigned m = __ballot_sync(0xFFFFFFFFu, key == kmax && v0 != 0);
            const int winner = __ffs(m) - 1;
            const u64 win = __shfl_sync(0xFFFFFFFFu, v0, winner);
            if (lane == winner) { v0 = v1; v1 = v2; v2 = 0; }
            if (lane == r) res = win;
        }
    } else {
        // ---- Exact fallback: pk unique per t, strict < gives ranked set ----
        const float* __restrict__ xb = x + (size_t)b * DIM_T * DIM_F + f;
        u64 prev = ~0ull;
        for (int r = 0; r < TOPK; ++r) {
            u64 best = 0;
            for (int t = lane; t < DIM_T2; t += 32) {
                const float e = xb[(size_t)(2 * t) * DIM_F];
                const float o = xb[(size_t)(2 * t) * DIM_F + DIM_F];
                const float h = e - o;
                const u64 pk  = pack_cand(fabsf(h), t, h);
                if (pk < prev && pk > best) best = pk;
            }
#pragma unroll
            for (int off = 16; off > 0; off >>= 1) {
                const u64 other = __shfl_xor_sync(0xFFFFFFFFu, best, off);
                if (other > best) best = other;
            }
            if (lane == r) res = best;
            prev = best;              // uniform across warp after reduction
        }
    }

    if (lane < TOPK && res != 0) {
        const u32 payv = (u32)res;
        float val = __uint_as_float((u32)(res >> 32)) * 0.5f;   // |h|*0.5
        if (payv & 1) val = -val;
        const int tt = (int)(payv >> 1);
        float* __restrict__ db = out_det + (size_t)b * DIM_T * DIM_F;
        const size_t r0 = (size_t)(2 * tt) * DIM_F + f;
        db[r0]         = val;
        db[r0 + DIM_F] = -val;
    }

    if (lane == 0) g_count[col] = 0u;     // restore invariant for next call
}

extern "C" void kernel_launch(void* const* d_in, const int* in_sizes, int n_in,
                              void* d_out, int out_size)
{
    const float* x = (const float*)d_in[0];
    float* out = (float*)d_out;
    const size_t N = (size_t)out_size / 2;    // elements in `main`
    float* det = out + N;

    dim3 grid1(DIM_F4 / 32, DIM_B, NC);       // 4 x 8 x 32 = 1024 blocks
    haar_pass1<<<grid1, NTHREADS>>>((const float4*)x,
                                    (float4*)out,
                                    (float4*)det);

    haar_pass2<<<DIM_B * DIM_F / 8, 256>>>(x, det);   // 512 blocks
}